// round 14
// baseline (speedup 1.0000x reference)
#include <cuda_runtime.h>
#include <cuda_bf16.h>
#include <math.h>
#include <cstdint>

#define D 128
#define MAXN 100096
#define MAXE 1600256
#define EPSL 1e-5f
#define TILE_M 64
#define THREADS 256
#define TSTR 136   // bf16 tile row stride (elems): 272B rows, conflict-free ldmatrix

// ---------------- scratch ----------------
__device__ float g_h0 [(size_t)MAXN * D];
__device__ float g_h1 [(size_t)MAXN * D];
__device__ float g_invdeg[MAXN];
__device__ int   g_deg[MAXN];
__device__ int   g_rowptr[MAXN + 1];
__device__ int   g_cursor[MAXN];
__device__ int   g_scantmp[MAXN];
__device__ int   g_blksums[256];
__device__ int   g_srcsorted[MAXE];
__device__ __nv_bfloat16 g_whi[7 * 128 * 128];
__device__ __nv_bfloat16 g_wlo[7 * 128 * 128];
__device__ __nv_bfloat16 g_agghi[(size_t)MAXN * D];
__device__ __nv_bfloat16 g_agglo[(size_t)MAXN * D];

// ---------------- helpers ----------------
__device__ __forceinline__ uint32_t pack_hi2(float a, float b) {
    __nv_bfloat16 ha = __float2bfloat16(a), hb = __float2bfloat16(b);
    return ((uint32_t)__bfloat16_as_ushort(hb) << 16) | __bfloat16_as_ushort(ha);
}
__device__ __forceinline__ uint32_t pack_lo2(float a, float b) {
    __nv_bfloat16 ha = __float2bfloat16(a), hb = __float2bfloat16(b);
    __nv_bfloat16 la = __float2bfloat16(a - __bfloat162float(ha));
    __nv_bfloat16 lb = __float2bfloat16(b - __bfloat162float(hb));
    return ((uint32_t)__bfloat16_as_ushort(lb) << 16) | __bfloat16_as_ushort(la);
}

// ---------------- CSR build ----------------
__global__ void k_zero(int* deg, int* rowptr, int N) {
    int i = blockIdx.x * blockDim.x + threadIdx.x;
    if (i < N) deg[i] = 0;
    if (i == 0) rowptr[0] = 0;
}
__global__ void k_count(const int* __restrict__ dst, int* __restrict__ deg, int E) {
    int e = blockIdx.x * blockDim.x + threadIdx.x;
    if (e < E) atomicAdd(&deg[dst[e]], 1);
}
__global__ void k_scan1(const int* __restrict__ deg, int* __restrict__ tmp,
                        int* __restrict__ blks, int N) {
    __shared__ int sm[1024];
    int i = blockIdx.x * 1024 + threadIdx.x;
    int v = (i < N) ? deg[i] : 0;
    sm[threadIdx.x] = v;
    __syncthreads();
    for (int o = 1; o < 1024; o <<= 1) {
        int t = (threadIdx.x >= o) ? sm[threadIdx.x - o] : 0;
        __syncthreads();
        sm[threadIdx.x] += t;
        __syncthreads();
    }
    if (i < N) tmp[i] = sm[threadIdx.x];
    if (threadIdx.x == 1023) blks[blockIdx.x] = sm[1023];
}
__global__ void k_scan3b(const int* __restrict__ tmp, const int* __restrict__ blks,
                         const int* __restrict__ deg,
                         int* __restrict__ rowptr, int* __restrict__ cursor,
                         float* __restrict__ invdeg, int N) {
    __shared__ int bp;
    if (threadIdx.x == 0) {
        int s = 0;
        for (int b = 0; b < (int)blockIdx.x; b++) s += blks[b];
        bp = s;
    }
    __syncthreads();
    int i = blockIdx.x * 1024 + threadIdx.x;
    if (i < N) {
        int rp1 = tmp[i] + bp;
        rowptr[i + 1] = rp1;
        int d = deg[i];
        cursor[i] = rp1 - d;
        invdeg[i] = 1.0f / (float)max(d, 1);
    }
    if (i == 0) rowptr[0] = 0;
}
__global__ void k_fill(const int* __restrict__ src, const int* __restrict__ dst,
                       int* __restrict__ cursor, int* __restrict__ srcs, int E) {
    int e = blockIdx.x * blockDim.x + threadIdx.x;
    if (e < E) {
        int p = atomicAdd(&cursor[dst[e]], 1);
        srcs[p] = src[e];
    }
}

// ---------------- weight split fp32 -> bf16 hi/lo ----------------
__global__ void k_wsplit(const float* __restrict__ proj_w, const float* __restrict__ lin_l_w,
                         const float* __restrict__ lin_r_w,
                         __nv_bfloat16* __restrict__ whi, __nv_bfloat16* __restrict__ wlo) {
    int i = blockIdx.x * blockDim.x + threadIdx.x;
    if (i >= 7 * 16384) return;
    int m = i >> 14, e = i & 16383;
    float v = (m == 0) ? proj_w[e] : (m <= 3 ? lin_l_w[(m - 1) * 16384 + e]
                                             : lin_r_w[(m - 4) * 16384 + e]);
    __nv_bfloat16 h = __float2bfloat16(v);
    whi[i] = h;
    wlo[i] = __float2bfloat16(v - __bfloat162float(h));
}

// ---------------- mean aggregation: warp per node, x8 batched MLP ----------------
__global__ void k_aggregate(const float* __restrict__ h, const int* __restrict__ rowptr,
                            const int* __restrict__ srcs, const float* __restrict__ invdeg,
                            __nv_bfloat16* __restrict__ ahi, __nv_bfloat16* __restrict__ alo,
                            int N) {
    int node = blockIdx.x * (blockDim.x >> 5) + (threadIdx.x >> 5);
    if (node >= N) return;
    int lane = threadIdx.x & 31;
    float ax = 0.f, ay = 0.f, az = 0.f, aw = 0.f;
    int e0 = rowptr[node], e1 = rowptr[node + 1];
    int e = e0;
    for (; e + 7 < e1; e += 8) {
        int s0 = __ldg(&srcs[e]);
        int s1 = __ldg(&srcs[e + 1]);
        int s2 = __ldg(&srcs[e + 2]);
        int s3 = __ldg(&srcs[e + 3]);
        int s4 = __ldg(&srcs[e + 4]);
        int s5 = __ldg(&srcs[e + 5]);
        int s6 = __ldg(&srcs[e + 6]);
        int s7 = __ldg(&srcs[e + 7]);
        float4 v0 = __ldg((const float4*)(h + (size_t)s0 * D + lane * 4));
        float4 v1 = __ldg((const float4*)(h + (size_t)s1 * D + lane * 4));
        float4 v2 = __ldg((const float4*)(h + (size_t)s2 * D + lane * 4));
        float4 v3 = __ldg((const float4*)(h + (size_t)s3 * D + lane * 4));
        float4 v4 = __ldg((const float4*)(h + (size_t)s4 * D + lane * 4));
        float4 v5 = __ldg((const float4*)(h + (size_t)s5 * D + lane * 4));
        float4 v6 = __ldg((const float4*)(h + (size_t)s6 * D + lane * 4));
        float4 v7 = __ldg((const float4*)(h + (size_t)s7 * D + lane * 4));
        ax += (v0.x + v1.x) + (v2.x + v3.x) + (v4.x + v5.x) + (v6.x + v7.x);
        ay += (v0.y + v1.y) + (v2.y + v3.y) + (v4.y + v5.y) + (v6.y + v7.y);
        az += (v0.z + v1.z) + (v2.z + v3.z) + (v4.z + v5.z) + (v6.z + v7.z);
        aw += (v0.w + v1.w) + (v2.w + v3.w) + (v4.w + v5.w) + (v6.w + v7.w);
    }
    for (; e + 3 < e1; e += 4) {
        int s0 = __ldg(&srcs[e]);
        int s1 = __ldg(&srcs[e + 1]);
        int s2 = __ldg(&srcs[e + 2]);
        int s3 = __ldg(&srcs[e + 3]);
        float4 v0 = __ldg((const float4*)(h + (size_t)s0 * D + lane * 4));
        float4 v1 = __ldg((const float4*)(h + (size_t)s1 * D + lane * 4));
        float4 v2 = __ldg((const float4*)(h + (size_t)s2 * D + lane * 4));
        float4 v3 = __ldg((const float4*)(h + (size_t)s3 * D + lane * 4));
        ax += v0.x + v1.x + v2.x + v3.x;
        ay += v0.y + v1.y + v2.y + v3.y;
        az += v0.z + v1.z + v2.z + v3.z;
        aw += v0.w + v1.w + v2.w + v3.w;
    }
    for (; e < e1; e++) {
        int s = __ldg(&srcs[e]);
        float4 v = __ldg((const float4*)(h + (size_t)s * D + lane * 4));
        ax += v.x; ay += v.y; az += v.z; aw += v.w;
    }
    float id = invdeg[node];
    ax *= id; ay *= id; az *= id; aw *= id;
    size_t off = (size_t)node * D + lane * 4;
    *(uint2*)(ahi + off) = make_uint2(pack_hi2(ax, ay), pack_hi2(az, aw));
    *(uint2*)(alo + off) = make_uint2(pack_lo2(ax, ay), pack_lo2(az, aw));
}

// ---------------- mma.sync helpers ----------------
__device__ __forceinline__ void ldsm4(uint32_t* r, uint32_t saddr) {
    asm volatile("ldmatrix.sync.aligned.m8n8.x4.shared.b16 {%0,%1,%2,%3}, [%4];"
                 : "=r"(r[0]), "=r"(r[1]), "=r"(r[2]), "=r"(r[3]) : "r"(saddr));
}
__device__ __forceinline__ void mma_bf16(float* c, const uint32_t* a, uint32_t b0, uint32_t b1) {
    asm volatile(
        "mma.sync.aligned.m16n8k16.row.col.f32.bf16.bf16.f32 "
        "{%0,%1,%2,%3}, {%4,%5,%6,%7}, {%8,%9}, {%0,%1,%2,%3};"
        : "+f"(c[0]), "+f"(c[1]), "+f"(c[2]), "+f"(c[3])
        : "r"(a[0]), "r"(a[1]), "r"(a[2]), "r"(a[3]), "r"(b0), "r"(b1));
}

// =================== HMMA multi-GEMM + bias/relu/LN/resid (+head) ===================
// Block = 64x128 tile, 256 threads, warp grid 2(M)x4(N); warp tile 32x32. 2 CTAs/SM.
// Passes: 0 = A1(agg, pre-split) @ W1; 1 = A2f(h fp32, split in-kernel) @ W2;
//         2 (optional) = reuse A2 tile @ W3 -> acc2 (fused input-proj residual).
#define OFF_AHI 0
#define OFF_ALO (TILE_M * TSTR * 2)
#define OFF_BHI (2 * TILE_M * TSTR * 2)
#define OFF_BLO (OFF_BHI + 128 * TSTR * 2)
#define OFF_PAR (OFF_BLO + 128 * TSTR * 2)
#define SMEM_BYTES (OFF_PAR + 5 * 512)

__global__ void __launch_bounds__(THREADS, 2)
k_tcgemm(const __nv_bfloat16* __restrict__ A1hi, const __nv_bfloat16* __restrict__ A1lo,
         const float* __restrict__ A2f,
         const __nv_bfloat16* __restrict__ Whi1, const __nv_bfloat16* __restrict__ Wlo1,
         const __nv_bfloat16* __restrict__ Whi2, const __nv_bfloat16* __restrict__ Wlo2,
         const __nv_bfloat16* __restrict__ Whi3, const __nv_bfloat16* __restrict__ Wlo3,
         const float* __restrict__ bias, const float* __restrict__ pb,
         const float* __restrict__ lng, const float* __restrict__ lnb,
         const float* __restrict__ resid,
         float* __restrict__ outp,
         const float* __restrict__ hw, const float* __restrict__ hb,
         const float* __restrict__ rer, const float* __restrict__ alpha,
         float* __restrict__ score, int M) {
    extern __shared__ __align__(16) char sg[];
    uint32_t sb = (uint32_t)__cvta_generic_to_shared(sg);

    int tid  = threadIdx.x;
    int lane = tid & 31;
    int wid  = tid >> 5;
    int wm   = wid >> 2;          // m offset wm*32
    int wn   = wid & 3;           // n offset wn*32
    int row0 = blockIdx.x * TILE_M;

    float* bias_s = (float*)(sg + OFF_PAR);
    float* lng_s  = (float*)(sg + OFF_PAR + 512);
    float* lnb_s  = (float*)(sg + OFF_PAR + 1024);
    float* hw_s   = (float*)(sg + OFF_PAR + 1536);
    float* pb_s   = (float*)(sg + OFF_PAR + 2048);
    float* Sg     = (float*)sg;                 // acc staging 64x132 fp32
    float* Sg2    = (float*)sg + 64 * 132;      // acc2 staging (proj residual)

    if (tid < 128) {
        bias_s[tid] = bias ? bias[tid] : 0.f;
        lng_s[tid]  = lng ? lng[tid] : 1.f;
        lnb_s[tid]  = lnb ? lnb[tid] : 0.f;
        hw_s[tid]   = hw  ? hw[tid]  : 0.f;
        pb_s[tid]   = pb  ? pb[tid]  : 0.f;
    }

    float acc[2][4][4], acc2[2][4][4];
#pragma unroll
    for (int mt = 0; mt < 2; mt++)
#pragma unroll
        for (int nt = 0; nt < 4; nt++)
#pragma unroll
            for (int c = 0; c < 4; c++) { acc[mt][nt][c] = 0.f; acc2[mt][nt][c] = 0.f; }

    int frow = lane & 15;
    int fcol = (lane >> 4) * 8;
    uint32_t aoff = (uint32_t)(((wm * 32 + frow) * TSTR + fcol) * 2);
    uint32_t boff = (uint32_t)(((wn * 32 + frow) * TSTR + fcol) * 2);

    auto mma_phase = [&](float (*ac)[4][4]) {
#pragma unroll
        for (int ks = 0; ks < 8; ks++) {
            uint32_t kb = (uint32_t)(ks * 32);
            uint32_t ah[2][4], al[2][4], bh[2][4], bl[2][4];
#pragma unroll
            for (int mt = 0; mt < 2; mt++) {
                ldsm4(ah[mt], sb + OFF_AHI + aoff + mt * 16 * TSTR * 2 + kb);
                ldsm4(al[mt], sb + OFF_ALO + aoff + mt * 16 * TSTR * 2 + kb);
            }
#pragma unroll
            for (int p = 0; p < 2; p++) {
                ldsm4(bh[p], sb + OFF_BHI + boff + p * 16 * TSTR * 2 + kb);
                ldsm4(bl[p], sb + OFF_BLO + boff + p * 16 * TSTR * 2 + kb);
            }
#pragma unroll
            for (int mt = 0; mt < 2; mt++) {
#pragma unroll
                for (int nt = 0; nt < 4; nt++) {
                    int p = nt >> 1, q = nt & 1;
                    mma_bf16(ac[mt][nt], ah[mt], bh[p][q], bh[p][q + 2]);  // hi*hi
                    mma_bf16(ac[mt][nt], ah[mt], bl[p][q], bl[p][q + 2]);  // hi*lo
                    mma_bf16(ac[mt][nt], al[mt], bh[p][q], bh[p][q + 2]);  // lo*hi
                }
            }
        }
    };

    int npass = (Whi3 != nullptr) ? 3 : 2;
    const __nv_bfloat16* Whis[3] = {Whi1, Whi2, Whi3};
    const __nv_bfloat16* Wlos[3] = {Wlo1, Wlo2, Wlo3};

    for (int pass = 0; pass < npass; pass++) {
        const __nv_bfloat16* Whi = Whis[pass];
        const __nv_bfloat16* Wlo = Wlos[pass];

        // W tiles via cp.async: 128 rows x 16 chunks of 16B
#pragma unroll
        for (int it = 0; it < 8; it++) {
            int u = tid + it * 256;
            int n = u >> 4, c16 = u & 15;
            uint32_t doff = (uint32_t)(n * TSTR * 2 + c16 * 16);
            const size_t gs = (size_t)n * 128 + c16 * 8;
            asm volatile("cp.async.ca.shared.global [%0], [%1], 16;"
                         :: "r"(sb + OFF_BHI + doff), "l"(Whi + gs));
            asm volatile("cp.async.ca.shared.global [%0], [%1], 16;"
                         :: "r"(sb + OFF_BLO + doff), "l"(Wlo + gs));
        }

        if (pass == 0) {
            // pre-split A1 (agg): cp.async, 64 rows x 16 chunks
#pragma unroll
            for (int it = 0; it < 4; it++) {
                int u = tid + it * 256;
                int r = u >> 4, c16 = u & 15;
                uint32_t doff = (uint32_t)(r * TSTR * 2 + c16 * 16);
                const size_t gs = (size_t)(row0 + r) * D + c16 * 8;
                asm volatile("cp.async.ca.shared.global [%0], [%1], 16;"
                             :: "r"(sb + OFF_AHI + doff), "l"(A1hi + gs));
                asm volatile("cp.async.ca.shared.global [%0], [%1], 16;"
                             :: "r"(sb + OFF_ALO + doff), "l"(A1lo + gs));
            }
            asm volatile("cp.async.commit_group;");
        } else if (pass == 1) {
            asm volatile("cp.async.commit_group;");
            // fp32 A2 -> split in-kernel
#pragma unroll
            for (int it = 0; it < 8; it++) {
                int idx = tid + it * 256;
                int r = idx >> 5, k4 = (idx & 31);
                float4 v = make_float4(0.f, 0.f, 0.f, 0.f);
                int grow = row0 + r;
                if (grow < M) v = *(const float4*)(A2f + (size_t)grow * D + k4 * 4);
                int doff = r * TSTR * 2 + k4 * 8;
                *(uint2*)(sg + OFF_AHI + doff) = make_uint2(pack_hi2(v.x, v.y), pack_hi2(v.z, v.w));
                *(uint2*)(sg + OFF_ALO + doff) = make_uint2(pack_lo2(v.x, v.y), pack_lo2(v.z, v.w));
            }
        } else {
            asm volatile("cp.async.commit_group;");
            // pass 2: reuse A tile from pass 1
        }

        asm volatile("cp.async.wait_group 0;");
        __syncthreads();

        if (pass == 2) mma_phase(acc2);
        else           mma_phase(acc);
        __syncthreads();
    }

    // ---- stage accumulators to SMEM ----
#pragma unroll
    for (int mt = 0; mt < 2; mt++) {
#pragma unroll
        for (int nt = 0; nt < 4; nt++) {
            int m = wm * 32 + mt * 16 + (lane >> 2);
            int n = wn * 32 + nt * 8 + (lane & 3) * 2;
            *(float2*)&Sg[m * 132 + n]       = make_float2(acc[mt][nt][0], acc[mt][nt][1]);
            *(float2*)&Sg[(m + 8) * 132 + n] = make_float2(acc[mt][nt][2], acc[mt][nt][3]);
            if (npass == 3) {
                *(float2*)&Sg2[m * 132 + n]       = make_float2(acc2[mt][nt][0], acc2[mt][nt][1]);
                *(float2*)&Sg2[(m + 8) * 132 + n] = make_float2(acc2[mt][nt][2], acc2[mt][nt][3]);
            }
        }
    }
    __syncthreads();

    // ---- per-row epilogue; warp owns 8 rows, lane owns cols lane*4..+3 ----
    int cb = lane * 4;
#pragma unroll
    for (int rr = 0; rr < 8; rr++) {
        int row_l = wid * 8 + rr;
        int grow = row0 + row_l;
        if (grow >= M) break;
        float v[4];
#pragma unroll
        for (int cc = 0; cc < 4; cc++)
            v[cc] = Sg[row_l * 132 + cb + cc] + bias_s[cb + cc];
        // relu + LN
#pragma unroll
        for (int cc = 0; cc < 4; cc++) v[cc] = fmaxf(v[cc], 0.f);
        float s = v[0] + v[1] + v[2] + v[3];
#pragma unroll
        for (int o = 16; o > 0; o >>= 1) s += __shfl_xor_sync(0xffffffffu, s, o);
        float mu = s * (1.f / 128.f);
        float d0 = v[0] - mu, d1 = v[1] - mu, d2 = v[2] - mu, d3 = v[3] - mu;
        float q = d0 * d0 + d1 * d1 + d2 * d2 + d3 * d3;
#pragma unroll
        for (int o = 16; o > 0; o >>= 1) q += __shfl_xor_sync(0xffffffffu, q, o);
        float rs = rsqrtf(q * (1.f / 128.f) + EPSL);
        v[0] = d0 * rs * lng_s[cb]     + lnb_s[cb];
        v[1] = d1 * rs * lng_s[cb + 1] + lnb_s[cb + 1];
        v[2] = d2 * rs * lng_s[cb + 2] + lnb_s[cb + 2];
        v[3] = d3 * rs * lng_s[cb + 3] + lnb_s[cb + 3];
        if (npass == 3) {
            // fused input-proj residual: acc2 + proj_b
#pragma unroll
            for (int cc = 0; cc < 4; cc++)
                v[cc] += Sg2[row_l * 132 + cb + cc] + pb_s[cb + cc];
        } else {
            float4 rz = *(const float4*)(resid + (size_t)grow * D + cb);
            v[0] += rz.x; v[1] += rz.y; v[2] += rz.z; v[3] += rz.w;
        }
        if (score) {
            float sd = v[0] * hw_s[cb] + v[1] * hw_s[cb + 1]
                     + v[2] * hw_s[cb + 2] + v[3] * hw_s[cb + 3];
#pragma unroll
            for (int o = 16; o > 0; o >>= 1) sd += __shfl_xor_sync(0xffffffffu, sd, o);
            if (lane == 0) {
                float gnn = sd + hb[0];
                float a = 1.f / (1.f + expf(-alpha[0]));
                score[grow] = a * rer[grow] + (1.f - a) * gnn;
            }
        } else {
            *(float4*)(outp + (size_t)grow * D + cb) = make_float4(v[0], v[1], v[2], v[3]);
        }
    }
}

// ---------------- launch ----------------
extern "C" void kernel_launch(void* const* d_in, const int* in_sizes, int n_in,
                              void* d_out, int out_size) {
    const float* x       = (const float*)d_in[0];
    const int*   ei      = (const int*)  d_in[1];
    const float* rer     = (const float*)d_in[2];
    const float* proj_w  = (const float*)d_in[3];
    const float* proj_b  = (const float*)d_in[4];
    const float* lin_l_w = (const float*)d_in[5];
    const float* lin_l_b = (const float*)d_in[6];
    const float* lin_r_w = (const float*)d_in[7];
    const float* ln_g    = (const float*)d_in[8];
    const float* ln_b    = (const float*)d_in[9];
    const float* head_w  = (const float*)d_in[10];
    const float* head_b  = (const float*)d_in[11];
    const float* alpha   = (const float*)d_in[12];

    int N = in_sizes[0] / D;
    int E = in_sizes[1] / 2;
    const int* src = ei;
    const int* dst = ei + E;
    float* out = (float*)d_out;

    float *h0, *h1, *invdeg;
    int *deg, *rowptr, *cursor, *stmp, *blks, *srcs;
    __nv_bfloat16 *whi, *wlo, *ahi, *alo;
    cudaGetSymbolAddress((void**)&h0,     g_h0);
    cudaGetSymbolAddress((void**)&h1,     g_h1);
    cudaGetSymbolAddress((void**)&invdeg, g_invdeg);
    cudaGetSymbolAddress((void**)&deg,    g_deg);
    cudaGetSymbolAddress((void**)&rowptr, g_rowptr);
    cudaGetSymbolAddress((void**)&cursor, g_cursor);
    cudaGetSymbolAddress((void**)&stmp,   g_scantmp);
    cudaGetSymbolAddress((void**)&blks,   g_blksums);
    cudaGetSymbolAddress((void**)&srcs,   g_srcsorted);
    cudaGetSymbolAddress((void**)&whi,    g_whi);
    cudaGetSymbolAddress((void**)&wlo,    g_wlo);
    cudaGetSymbolAddress((void**)&ahi,    g_agghi);
    cudaGetSymbolAddress((void**)&alo,    g_agglo);

    // lazy one-time stream/event creation (no device memory allocation)
    static cudaStream_t s2 = nullptr;
    static cudaEvent_t evFork = nullptr, evJoin = nullptr;
    if (s2 == nullptr) {
        cudaStreamCreateWithFlags(&s2, cudaStreamNonBlocking);
        cudaEventCreateWithFlags(&evFork, cudaEventDisableTiming);
        cudaEventCreateWithFlags(&evJoin, cudaEventDisableTiming);
    }

    int nb = (N + 1023) / 1024;
    cudaFuncSetAttribute(k_tcgemm, cudaFuncAttributeMaxDynamicSharedMemorySize, SMEM_BYTES);
    int blocks = (N + TILE_M - 1) / TILE_M;
    int warp_blocks = (N + 7) / 8;
    const size_t WM = 128 * 128;

    // ---- fork: branch B (s2) = wsplit; branch A (default) = CSR ----
    cudaEventRecord(evFork, 0);
    cudaStreamWaitEvent(s2, evFork, 0);

    k_wsplit<<<(7 * 16384 + 255) / 256, 256, 0, s2>>>(proj_w, lin_l_w, lin_r_w, whi, wlo);

    k_zero  <<<(N + 255) / 256, 256>>>(deg, rowptr, N);
    k_count <<<(E + 255) / 256, 256>>>(dst, deg, E);
    k_scan1 <<<nb, 1024>>>(deg, stmp, blks, N);
    k_scan3b<<<nb, 1024>>>(stmp, blks, deg, rowptr, cursor, invdeg, N);
    k_fill  <<<(E + 255) / 256, 256>>>(src, dst, cursor, srcs, E);

    cudaEventRecord(evJoin, s2);
    cudaStreamWaitEvent(0, evJoin, 0);

    // ---- layers; layer 0 fuses the input-proj residual as a 3rd MMA pass ----
    const float* h_cur = x;
    float* bufs[2] = {h0, h1};
    for (int i = 0; i < 3; i++) {
        bool last = (i == 2);
        k_aggregate<<<warp_blocks, 256>>>(h_cur, rowptr, srcs, invdeg, ahi, alo, N);
        k_tcgemm<<<blocks, THREADS, SMEM_BYTES>>>(
            ahi, alo, h_cur,
            whi + (1 + i) * WM, wlo + (1 + i) * WM,
            whi + (4 + i) * WM, wlo + (4 + i) * WM,
            (i == 0) ? whi : nullptr,          // W3 = proj (layer 0 only)
            (i == 0) ? wlo : nullptr,
            lin_l_b + (size_t)i * D,
            (i == 0) ? proj_b : nullptr,
            ln_g + (size_t)i * D, ln_b + (size_t)i * D,
            (i == 0) ? nullptr : h_cur,        // resid: global h for layers 1,2
            last ? nullptr : bufs[i & 1],
            last ? head_w : nullptr,
            last ? head_b : nullptr,
            last ? rer    : nullptr,
            last ? alpha  : nullptr,
            last ? out    : nullptr, N);
        h_cur = bufs[i & 1];
    }
}

// round 15
// speedup vs baseline: 1.4132x; 1.4132x over previous
#include <cuda_runtime.h>
#include <cuda_bf16.h>
#include <math.h>
#include <cstdint>

#define D 128
#define MAXN 100096
#define MAXE 1600256
#define EPSL 1e-5f
#define TILE_M 64
#define THREADS 256
#define TSTR 136   // bf16 tile row stride (elems): 272B rows, conflict-free ldmatrix

// ---------------- scratch ----------------
__device__ float g_h0 [(size_t)MAXN * D];
__device__ float g_h1 [(size_t)MAXN * D];
__device__ float g_invdeg[MAXN];
__device__ int   g_deg[MAXN];
__device__ int   g_rowptr[MAXN + 1];
__device__ int   g_cursor[MAXN];
__device__ int   g_scantmp[MAXN];
__device__ int   g_blksums[256];
__device__ int   g_srcsorted[MAXE];
__device__ __nv_bfloat16 g_whi[7 * 128 * 128];
__device__ __nv_bfloat16 g_wlo[7 * 128 * 128];
__device__ __nv_bfloat16 g_agghi[(size_t)MAXN * D];
__device__ __nv_bfloat16 g_agglo[(size_t)MAXN * D];

// ---------------- helpers ----------------
__device__ __forceinline__ uint32_t pack_hi2(float a, float b) {
    __nv_bfloat16 ha = __float2bfloat16(a), hb = __float2bfloat16(b);
    return ((uint32_t)__bfloat16_as_ushort(hb) << 16) | __bfloat16_as_ushort(ha);
}
__device__ __forceinline__ uint32_t pack_lo2(float a, float b) {
    __nv_bfloat16 ha = __float2bfloat16(a), hb = __float2bfloat16(b);
    __nv_bfloat16 la = __float2bfloat16(a - __bfloat162float(ha));
    __nv_bfloat16 lb = __float2bfloat16(b - __bfloat162float(hb));
    return ((uint32_t)__bfloat16_as_ushort(lb) << 16) | __bfloat16_as_ushort(la);
}

// ---------------- CSR build ----------------
__global__ void k_zero(int* deg, int* rowptr, int N) {
    int i = blockIdx.x * blockDim.x + threadIdx.x;
    if (i < N) deg[i] = 0;
    if (i == 0) rowptr[0] = 0;
}
__global__ void k_count(const int* __restrict__ dst, int* __restrict__ deg, int E) {
    int e = blockIdx.x * blockDim.x + threadIdx.x;
    if (e < E) atomicAdd(&deg[dst[e]], 1);
}
__global__ void k_scan1(const int* __restrict__ deg, int* __restrict__ tmp,
                        int* __restrict__ blks, int N) {
    __shared__ int sm[1024];
    int i = blockIdx.x * 1024 + threadIdx.x;
    int v = (i < N) ? deg[i] : 0;
    sm[threadIdx.x] = v;
    __syncthreads();
    for (int o = 1; o < 1024; o <<= 1) {
        int t = (threadIdx.x >= o) ? sm[threadIdx.x - o] : 0;
        __syncthreads();
        sm[threadIdx.x] += t;
        __syncthreads();
    }
    if (i < N) tmp[i] = sm[threadIdx.x];
    if (threadIdx.x == 1023) blks[blockIdx.x] = sm[1023];
}
__global__ void k_scan3b(const int* __restrict__ tmp, const int* __restrict__ blks,
                         const int* __restrict__ deg,
                         int* __restrict__ rowptr, int* __restrict__ cursor,
                         float* __restrict__ invdeg, int N) {
    __shared__ int bp;
    if (threadIdx.x == 0) {
        int s = 0;
        for (int b = 0; b < (int)blockIdx.x; b++) s += blks[b];
        bp = s;
    }
    __syncthreads();
    int i = blockIdx.x * 1024 + threadIdx.x;
    if (i < N) {
        int rp1 = tmp[i] + bp;
        rowptr[i + 1] = rp1;
        int d = deg[i];
        cursor[i] = rp1 - d;
        invdeg[i] = 1.0f / (float)max(d, 1);
    }
    if (i == 0) rowptr[0] = 0;
}
__global__ void k_fill(const int* __restrict__ src, const int* __restrict__ dst,
                       int* __restrict__ cursor, int* __restrict__ srcs, int E) {
    int e = blockIdx.x * blockDim.x + threadIdx.x;
    if (e < E) {
        int p = atomicAdd(&cursor[dst[e]], 1);
        srcs[p] = src[e];
    }
}

// ---------------- weight split fp32 -> bf16 hi/lo ----------------
__global__ void k_wsplit(const float* __restrict__ proj_w, const float* __restrict__ lin_l_w,
                         const float* __restrict__ lin_r_w,
                         __nv_bfloat16* __restrict__ whi, __nv_bfloat16* __restrict__ wlo) {
    int i = blockIdx.x * blockDim.x + threadIdx.x;
    if (i >= 7 * 16384) return;
    int m = i >> 14, e = i & 16383;
    float v = (m == 0) ? proj_w[e] : (m <= 3 ? lin_l_w[(m - 1) * 16384 + e]
                                             : lin_r_w[(m - 4) * 16384 + e]);
    __nv_bfloat16 h = __float2bfloat16(v);
    whi[i] = h;
    wlo[i] = __float2bfloat16(v - __bfloat162float(h));
}

// ---------------- mean aggregation: warp per node, x4 unrolled, src prefetch ------
__global__ void k_aggregate(const float* __restrict__ h, const int* __restrict__ rowptr,
                            const int* __restrict__ srcs, const float* __restrict__ invdeg,
                            __nv_bfloat16* __restrict__ ahi, __nv_bfloat16* __restrict__ alo,
                            int N) {
    int node = blockIdx.x * (blockDim.x >> 5) + (threadIdx.x >> 5);
    if (node >= N) return;
    int lane = threadIdx.x & 31;
    float ax = 0.f, ay = 0.f, az = 0.f, aw = 0.f;
    int e0 = rowptr[node], e1 = rowptr[node + 1];
    int e = e0;
    if (e + 3 < e1) {
        // prime the index pipeline
        int s0 = __ldg(&srcs[e]);
        int s1 = __ldg(&srcs[e + 1]);
        int s2 = __ldg(&srcs[e + 2]);
        int s3 = __ldg(&srcs[e + 3]);
        for (; e + 7 < e1; e += 4) {
            // issue next 4 index loads early; they fly under the 4 row loads
            int n0 = __ldg(&srcs[e + 4]);
            int n1 = __ldg(&srcs[e + 5]);
            int n2 = __ldg(&srcs[e + 6]);
            int n3 = __ldg(&srcs[e + 7]);
            float4 v0 = __ldg((const float4*)(h + (size_t)s0 * D + lane * 4));
            float4 v1 = __ldg((const float4*)(h + (size_t)s1 * D + lane * 4));
            float4 v2 = __ldg((const float4*)(h + (size_t)s2 * D + lane * 4));
            float4 v3 = __ldg((const float4*)(h + (size_t)s3 * D + lane * 4));
            ax += v0.x + v1.x + v2.x + v3.x;
            ay += v0.y + v1.y + v2.y + v3.y;
            az += v0.z + v1.z + v2.z + v3.z;
            aw += v0.w + v1.w + v2.w + v3.w;
            s0 = n0; s1 = n1; s2 = n2; s3 = n3;
        }
        // drain the primed batch
        float4 v0 = __ldg((const float4*)(h + (size_t)s0 * D + lane * 4));
        float4 v1 = __ldg((const float4*)(h + (size_t)s1 * D + lane * 4));
        float4 v2 = __ldg((const float4*)(h + (size_t)s2 * D + lane * 4));
        float4 v3 = __ldg((const float4*)(h + (size_t)s3 * D + lane * 4));
        ax += v0.x + v1.x + v2.x + v3.x;
        ay += v0.y + v1.y + v2.y + v3.y;
        az += v0.z + v1.z + v2.z + v3.z;
        aw += v0.w + v1.w + v2.w + v3.w;
        e += 4;
    }
    for (; e < e1; e++) {
        int s = __ldg(&srcs[e]);
        float4 v = __ldg((const float4*)(h + (size_t)s * D + lane * 4));
        ax += v.x; ay += v.y; az += v.z; aw += v.w;
    }
    float id = invdeg[node];
    ax *= id; ay *= id; az *= id; aw *= id;
    size_t off = (size_t)node * D + lane * 4;
    *(uint2*)(ahi + off) = make_uint2(pack_hi2(ax, ay), pack_hi2(az, aw));
    *(uint2*)(alo + off) = make_uint2(pack_lo2(ax, ay), pack_lo2(az, aw));
}

// ---------------- mma.sync helpers ----------------
__device__ __forceinline__ void ldsm4(uint32_t* r, uint32_t saddr) {
    asm volatile("ldmatrix.sync.aligned.m8n8.x4.shared.b16 {%0,%1,%2,%3}, [%4];"
                 : "=r"(r[0]), "=r"(r[1]), "=r"(r[2]), "=r"(r[3]) : "r"(saddr));
}
__device__ __forceinline__ void mma_bf16(float* c, const uint32_t* a, uint32_t b0, uint32_t b1) {
    asm volatile(
        "mma.sync.aligned.m16n8k16.row.col.f32.bf16.bf16.f32 "
        "{%0,%1,%2,%3}, {%4,%5,%6,%7}, {%8,%9}, {%0,%1,%2,%3};"
        : "+f"(c[0]), "+f"(c[1]), "+f"(c[2]), "+f"(c[3])
        : "r"(a[0]), "r"(a[1]), "r"(a[2]), "r"(a[3]), "r"(b0), "r"(b1));
}

// =================== HMMA multi-GEMM + bias/relu/LN/resid (+head) ===================
// Block = 64x128 tile, 256 threads, warp grid 2(M)x4(N); warp tile 32x32. 2 CTAs/SM.
// Passes: 0 = A1(agg, pre-split) @ W1; 1 = A2f(h fp32, split in-kernel) @ W2;
//         2 (optional) = reuse A2 tile @ W3 -> acc2 (fused input-proj residual).
#define OFF_AHI 0
#define OFF_ALO (TILE_M * TSTR * 2)
#define OFF_BHI (2 * TILE_M * TSTR * 2)
#define OFF_BLO (OFF_BHI + 128 * TSTR * 2)
#define OFF_PAR (OFF_BLO + 128 * TSTR * 2)
#define SMEM_BYTES (OFF_PAR + 5 * 512)

__global__ void __launch_bounds__(THREADS, 2)
k_tcgemm(const __nv_bfloat16* __restrict__ A1hi, const __nv_bfloat16* __restrict__ A1lo,
         const float* __restrict__ A2f,
         const __nv_bfloat16* __restrict__ Whi1, const __nv_bfloat16* __restrict__ Wlo1,
         const __nv_bfloat16* __restrict__ Whi2, const __nv_bfloat16* __restrict__ Wlo2,
         const __nv_bfloat16* __restrict__ Whi3, const __nv_bfloat16* __restrict__ Wlo3,
         const float* __restrict__ bias, const float* __restrict__ pb,
         const float* __restrict__ lng, const float* __restrict__ lnb,
         const float* __restrict__ resid,
         float* __restrict__ outp,
         const float* __restrict__ hw, const float* __restrict__ hb,
         const float* __restrict__ rer, const float* __restrict__ alpha,
         float* __restrict__ score, int M) {
    extern __shared__ __align__(16) char sg[];
    uint32_t sb = (uint32_t)__cvta_generic_to_shared(sg);

    int tid  = threadIdx.x;
    int lane = tid & 31;
    int wid  = tid >> 5;
    int wm   = wid >> 2;          // m offset wm*32
    int wn   = wid & 3;           // n offset wn*32
    int row0 = blockIdx.x * TILE_M;

    float* bias_s = (float*)(sg + OFF_PAR);
    float* lng_s  = (float*)(sg + OFF_PAR + 512);
    float* lnb_s  = (float*)(sg + OFF_PAR + 1024);
    float* hw_s   = (float*)(sg + OFF_PAR + 1536);
    float* pb_s   = (float*)(sg + OFF_PAR + 2048);
    float* Sg     = (float*)sg;                 // acc staging 64x132 fp32
    float* Sg2    = (float*)sg + 64 * 132;      // acc2 staging (proj residual)

    if (tid < 128) {
        bias_s[tid] = bias ? bias[tid] : 0.f;
        lng_s[tid]  = lng ? lng[tid] : 1.f;
        lnb_s[tid]  = lnb ? lnb[tid] : 0.f;
        hw_s[tid]   = hw  ? hw[tid]  : 0.f;
        pb_s[tid]   = pb  ? pb[tid]  : 0.f;
    }

    float acc[2][4][4], acc2[2][4][4];
#pragma unroll
    for (int mt = 0; mt < 2; mt++)
#pragma unroll
        for (int nt = 0; nt < 4; nt++)
#pragma unroll
            for (int c = 0; c < 4; c++) { acc[mt][nt][c] = 0.f; acc2[mt][nt][c] = 0.f; }

    int frow = lane & 15;
    int fcol = (lane >> 4) * 8;
    uint32_t aoff = (uint32_t)(((wm * 32 + frow) * TSTR + fcol) * 2);
    uint32_t boff = (uint32_t)(((wn * 32 + frow) * TSTR + fcol) * 2);

    auto mma_phase = [&](float (*ac)[4][4]) {
#pragma unroll
        for (int ks = 0; ks < 8; ks++) {
            uint32_t kb = (uint32_t)(ks * 32);
            uint32_t ah[2][4], al[2][4], bh[2][4], bl[2][4];
#pragma unroll
            for (int mt = 0; mt < 2; mt++) {
                ldsm4(ah[mt], sb + OFF_AHI + aoff + mt * 16 * TSTR * 2 + kb);
                ldsm4(al[mt], sb + OFF_ALO + aoff + mt * 16 * TSTR * 2 + kb);
            }
#pragma unroll
            for (int p = 0; p < 2; p++) {
                ldsm4(bh[p], sb + OFF_BHI + boff + p * 16 * TSTR * 2 + kb);
                ldsm4(bl[p], sb + OFF_BLO + boff + p * 16 * TSTR * 2 + kb);
            }
#pragma unroll
            for (int mt = 0; mt < 2; mt++) {
#pragma unroll
                for (int nt = 0; nt < 4; nt++) {
                    int p = nt >> 1, q = nt & 1;
                    mma_bf16(ac[mt][nt], ah[mt], bh[p][q], bh[p][q + 2]);  // hi*hi
                    mma_bf16(ac[mt][nt], ah[mt], bl[p][q], bl[p][q + 2]);  // hi*lo
                    mma_bf16(ac[mt][nt], al[mt], bh[p][q], bh[p][q + 2]);  // lo*hi
                }
            }
        }
    };

    int npass = (Whi3 != nullptr) ? 3 : 2;
    const __nv_bfloat16* Whis[3] = {Whi1, Whi2, Whi3};
    const __nv_bfloat16* Wlos[3] = {Wlo1, Wlo2, Wlo3};

    for (int pass = 0; pass < npass; pass++) {
        const __nv_bfloat16* Whi = Whis[pass];
        const __nv_bfloat16* Wlo = Wlos[pass];

        // W tiles via cp.async: 128 rows x 16 chunks of 16B
#pragma unroll
        for (int it = 0; it < 8; it++) {
            int u = tid + it * 256;
            int n = u >> 4, c16 = u & 15;
            uint32_t doff = (uint32_t)(n * TSTR * 2 + c16 * 16);
            const size_t gs = (size_t)n * 128 + c16 * 8;
            asm volatile("cp.async.ca.shared.global [%0], [%1], 16;"
                         :: "r"(sb + OFF_BHI + doff), "l"(Whi + gs));
            asm volatile("cp.async.ca.shared.global [%0], [%1], 16;"
                         :: "r"(sb + OFF_BLO + doff), "l"(Wlo + gs));
        }

        if (pass == 0) {
            // pre-split A1 (agg): cp.async, 64 rows x 16 chunks
#pragma unroll
            for (int it = 0; it < 4; it++) {
                int u = tid + it * 256;
                int r = u >> 4, c16 = u & 15;
                uint32_t doff = (uint32_t)(r * TSTR * 2 + c16 * 16);
                const size_t gs = (size_t)(row0 + r) * D + c16 * 8;
                asm volatile("cp.async.ca.shared.global [%0], [%1], 16;"
                             :: "r"(sb + OFF_AHI + doff), "l"(A1hi + gs));
                asm volatile("cp.async.ca.shared.global [%0], [%1], 16;"
                             :: "r"(sb + OFF_ALO + doff), "l"(A1lo + gs));
            }
            asm volatile("cp.async.commit_group;");
        } else if (pass == 1) {
            asm volatile("cp.async.commit_group;");
            // fp32 A2 -> split in-kernel
#pragma unroll
            for (int it = 0; it < 8; it++) {
                int idx = tid + it * 256;
                int r = idx >> 5, k4 = (idx & 31);
                float4 v = make_float4(0.f, 0.f, 0.f, 0.f);
                int grow = row0 + r;
                if (grow < M) v = *(const float4*)(A2f + (size_t)grow * D + k4 * 4);
                int doff = r * TSTR * 2 + k4 * 8;
                *(uint2*)(sg + OFF_AHI + doff) = make_uint2(pack_hi2(v.x, v.y), pack_hi2(v.z, v.w));
                *(uint2*)(sg + OFF_ALO + doff) = make_uint2(pack_lo2(v.x, v.y), pack_lo2(v.z, v.w));
            }
        } else {
            asm volatile("cp.async.commit_group;");
            // pass 2: reuse A tile from pass 1
        }

        asm volatile("cp.async.wait_group 0;");
        __syncthreads();

        if (pass == 2) mma_phase(acc2);
        else           mma_phase(acc);
        __syncthreads();
    }

    // ---- stage accumulators to SMEM ----
#pragma unroll
    for (int mt = 0; mt < 2; mt++) {
#pragma unroll
        for (int nt = 0; nt < 4; nt++) {
            int m = wm * 32 + mt * 16 + (lane >> 2);
            int n = wn * 32 + nt * 8 + (lane & 3) * 2;
            *(float2*)&Sg[m * 132 + n]       = make_float2(acc[mt][nt][0], acc[mt][nt][1]);
            *(float2*)&Sg[(m + 8) * 132 + n] = make_float2(acc[mt][nt][2], acc[mt][nt][3]);
            if (npass == 3) {
                *(float2*)&Sg2[m * 132 + n]       = make_float2(acc2[mt][nt][0], acc2[mt][nt][1]);
                *(float2*)&Sg2[(m + 8) * 132 + n] = make_float2(acc2[mt][nt][2], acc2[mt][nt][3]);
            }
        }
    }
    __syncthreads();

    // ---- per-row epilogue; warp owns 8 rows, lane owns cols lane*4..+3 ----
    int cb = lane * 4;
#pragma unroll
    for (int rr = 0; rr < 8; rr++) {
        int row_l = wid * 8 + rr;
        int grow = row0 + row_l;
        if (grow >= M) break;
        float v[4];
#pragma unroll
        for (int cc = 0; cc < 4; cc++)
            v[cc] = Sg[row_l * 132 + cb + cc] + bias_s[cb + cc];
        // relu + LN
#pragma unroll
        for (int cc = 0; cc < 4; cc++) v[cc] = fmaxf(v[cc], 0.f);
        float s = v[0] + v[1] + v[2] + v[3];
#pragma unroll
        for (int o = 16; o > 0; o >>= 1) s += __shfl_xor_sync(0xffffffffu, s, o);
        float mu = s * (1.f / 128.f);
        float d0 = v[0] - mu, d1 = v[1] - mu, d2 = v[2] - mu, d3 = v[3] - mu;
        float q = d0 * d0 + d1 * d1 + d2 * d2 + d3 * d3;
#pragma unroll
        for (int o = 16; o > 0; o >>= 1) q += __shfl_xor_sync(0xffffffffu, q, o);
        float rs = rsqrtf(q * (1.f / 128.f) + EPSL);
        v[0] = d0 * rs * lng_s[cb]     + lnb_s[cb];
        v[1] = d1 * rs * lng_s[cb + 1] + lnb_s[cb + 1];
        v[2] = d2 * rs * lng_s[cb + 2] + lnb_s[cb + 2];
        v[3] = d3 * rs * lng_s[cb + 3] + lnb_s[cb + 3];
        if (npass == 3) {
            // fused input-proj residual: acc2 + proj_b
#pragma unroll
            for (int cc = 0; cc < 4; cc++)
                v[cc] += Sg2[row_l * 132 + cb + cc] + pb_s[cb + cc];
        } else {
            float4 rz = *(const float4*)(resid + (size_t)grow * D + cb);
            v[0] += rz.x; v[1] += rz.y; v[2] += rz.z; v[3] += rz.w;
        }
        if (score) {
            float sd = v[0] * hw_s[cb] + v[1] * hw_s[cb + 1]
                     + v[2] * hw_s[cb + 2] + v[3] * hw_s[cb + 3];
#pragma unroll
            for (int o = 16; o > 0; o >>= 1) sd += __shfl_xor_sync(0xffffffffu, sd, o);
            if (lane == 0) {
                float gnn = sd + hb[0];
                float a = 1.f / (1.f + expf(-alpha[0]));
                score[grow] = a * rer[grow] + (1.f - a) * gnn;
            }
        } else {
            *(float4*)(outp + (size_t)grow * D + cb) = make_float4(v[0], v[1], v[2], v[3]);
        }
    }
}

// ---------------- launch ----------------
extern "C" void kernel_launch(void* const* d_in, const int* in_sizes, int n_in,
                              void* d_out, int out_size) {
    const float* x       = (const float*)d_in[0];
    const int*   ei      = (const int*)  d_in[1];
    const float* rer     = (const float*)d_in[2];
    const float* proj_w  = (const float*)d_in[3];
    const float* proj_b  = (const float*)d_in[4];
    const float* lin_l_w = (const float*)d_in[5];
    const float* lin_l_b = (const float*)d_in[6];
    const float* lin_r_w = (const float*)d_in[7];
    const float* ln_g    = (const float*)d_in[8];
    const float* ln_b    = (const float*)d_in[9];
    const float* head_w  = (const float*)d_in[10];
    const float* head_b  = (const float*)d_in[11];
    const float* alpha   = (const float*)d_in[12];

    int N = in_sizes[0] / D;
    int E = in_sizes[1] / 2;
    const int* src = ei;
    const int* dst = ei + E;
    float* out = (float*)d_out;

    float *h0, *h1, *invdeg;
    int *deg, *rowptr, *cursor, *stmp, *blks, *srcs;
    __nv_bfloat16 *whi, *wlo, *ahi, *alo;
    cudaGetSymbolAddress((void**)&h0,     g_h0);
    cudaGetSymbolAddress((void**)&h1,     g_h1);
    cudaGetSymbolAddress((void**)&invdeg, g_invdeg);
    cudaGetSymbolAddress((void**)&deg,    g_deg);
    cudaGetSymbolAddress((void**)&rowptr, g_rowptr);
    cudaGetSymbolAddress((void**)&cursor, g_cursor);
    cudaGetSymbolAddress((void**)&stmp,   g_scantmp);
    cudaGetSymbolAddress((void**)&blks,   g_blksums);
    cudaGetSymbolAddress((void**)&srcs,   g_srcsorted);
    cudaGetSymbolAddress((void**)&whi,    g_whi);
    cudaGetSymbolAddress((void**)&wlo,    g_wlo);
    cudaGetSymbolAddress((void**)&ahi,    g_agghi);
    cudaGetSymbolAddress((void**)&alo,    g_agglo);

    // lazy one-time stream/event creation (no device memory allocation)
    static cudaStream_t s2 = nullptr;
    static cudaEvent_t evFork = nullptr, evJoin = nullptr;
    if (s2 == nullptr) {
        cudaStreamCreateWithFlags(&s2, cudaStreamNonBlocking);
        cudaEventCreateWithFlags(&evFork, cudaEventDisableTiming);
        cudaEventCreateWithFlags(&evJoin, cudaEventDisableTiming);
    }

    int nb = (N + 1023) / 1024;
    cudaFuncSetAttribute(k_tcgemm, cudaFuncAttributeMaxDynamicSharedMemorySize, SMEM_BYTES);
    int blocks = (N + TILE_M - 1) / TILE_M;
    int warp_blocks = (N + 7) / 8;
    const size_t WM = 128 * 128;

    // ---- fork: branch B (s2) = wsplit; branch A (default) = CSR ----
    cudaEventRecord(evFork, 0);
    cudaStreamWaitEvent(s2, evFork, 0);

    k_wsplit<<<(7 * 16384 + 255) / 256, 256, 0, s2>>>(proj_w, lin_l_w, lin_r_w, whi, wlo);

    k_zero  <<<(N + 255) / 256, 256>>>(deg, rowptr, N);
    k_count <<<(E + 255) / 256, 256>>>(dst, deg, E);
    k_scan1 <<<nb, 1024>>>(deg, stmp, blks, N);
    k_scan3b<<<nb, 1024>>>(stmp, blks, deg, rowptr, cursor, invdeg, N);
    k_fill  <<<(E + 255) / 256, 256>>>(src, dst, cursor, srcs, E);

    cudaEventRecord(evJoin, s2);
    cudaStreamWaitEvent(0, evJoin, 0);

    // ---- layers; layer 0 fuses the input-proj residual as a 3rd MMA pass ----
    const float* h_cur = x;
    float* bufs[2] = {h0, h1};
    for (int i = 0; i < 3; i++) {
        bool last = (i == 2);
        k_aggregate<<<warp_blocks, 256>>>(h_cur, rowptr, srcs, invdeg, ahi, alo, N);
        k_tcgemm<<<blocks, THREADS, SMEM_BYTES>>>(
            ahi, alo, h_cur,
            whi + (1 + i) * WM, wlo + (1 + i) * WM,
            whi + (4 + i) * WM, wlo + (4 + i) * WM,
            (i == 0) ? whi : nullptr,          // W3 = proj (layer 0 only)
            (i == 0) ? wlo : nullptr,
            lin_l_b + (size_t)i * D,
            (i == 0) ? proj_b : nullptr,
            ln_g + (size_t)i * D, ln_b + (size_t)i * D,
            (i == 0) ? nullptr : h_cur,        // resid: global h for layers 1,2
            last ? nullptr : bufs[i & 1],
            last ? head_w : nullptr,
            last ? head_b : nullptr,
            last ? rer    : nullptr,
            last ? alpha  : nullptr,
            last ? out    : nullptr, N);
        h_cur = bufs[i & 1];
    }
}

// round 16
// speedup vs baseline: 1.4501x; 1.0261x over previous
#include <cuda_runtime.h>
#include <cuda_bf16.h>
#include <math.h>
#include <cstdint>

#define D 128
#define MAXN 100096
#define MAXE 1600256
#define EPSL 1e-5f
#define TILE_M 64
#define THREADS 256
#define TSTR 136   // bf16 tile row stride (elems): 272B rows, conflict-free ldmatrix

// ---------------- scratch ----------------
__device__ float g_h0 [(size_t)MAXN * D];
__device__ float g_h1 [(size_t)MAXN * D];
__device__ float g_invdeg[MAXN];
__device__ int   g_deg[MAXN];
__device__ int   g_rowptr[MAXN + 1];
__device__ int   g_cursor[MAXN];
__device__ int   g_scantmp[MAXN];
__device__ int   g_blksums[256];
__device__ int   g_srcsorted[MAXE];
__device__ __nv_bfloat16 g_whi[7 * 128 * 128];
__device__ __nv_bfloat16 g_wlo[7 * 128 * 128];
__device__ __nv_bfloat16 g_agghi[(size_t)MAXN * D];
__device__ __nv_bfloat16 g_agglo[(size_t)MAXN * D];

// ---------------- helpers ----------------
__device__ __forceinline__ uint32_t pack_hi2(float a, float b) {
    __nv_bfloat16 ha = __float2bfloat16(a), hb = __float2bfloat16(b);
    return ((uint32_t)__bfloat16_as_ushort(hb) << 16) | __bfloat16_as_ushort(ha);
}
__device__ __forceinline__ uint32_t pack_lo2(float a, float b) {
    __nv_bfloat16 ha = __float2bfloat16(a), hb = __float2bfloat16(b);
    __nv_bfloat16 la = __float2bfloat16(a - __bfloat162float(ha));
    __nv_bfloat16 lb = __float2bfloat16(b - __bfloat162float(hb));
    return ((uint32_t)__bfloat16_as_ushort(lb) << 16) | __bfloat16_as_ushort(la);
}

// ---------------- CSR build ----------------
__global__ void k_zero(int* deg, int* rowptr, int N) {
    int i = blockIdx.x * blockDim.x + threadIdx.x;
    if (i < N) deg[i] = 0;
    if (i == 0) rowptr[0] = 0;
}
// 4 edges per thread, int4 loads
__global__ void k_count4(const int* __restrict__ dst, int* __restrict__ deg, int E) {
    int q = blockIdx.x * blockDim.x + threadIdx.x;
    int e = q * 4;
    if (e + 3 < E) {
        int4 d = *(const int4*)(dst + e);
        atomicAdd(&deg[d.x], 1);
        atomicAdd(&deg[d.y], 1);
        atomicAdd(&deg[d.z], 1);
        atomicAdd(&deg[d.w], 1);
    } else {
        for (; e < E; e++) atomicAdd(&deg[dst[e]], 1);
    }
}
__global__ void k_scan1(const int* __restrict__ deg, int* __restrict__ tmp,
                        int* __restrict__ blks, int N) {
    __shared__ int sm[1024];
    int i = blockIdx.x * 1024 + threadIdx.x;
    int v = (i < N) ? deg[i] : 0;
    sm[threadIdx.x] = v;
    __syncthreads();
    for (int o = 1; o < 1024; o <<= 1) {
        int t = (threadIdx.x >= o) ? sm[threadIdx.x - o] : 0;
        __syncthreads();
        sm[threadIdx.x] += t;
        __syncthreads();
    }
    if (i < N) tmp[i] = sm[threadIdx.x];
    if (threadIdx.x == 1023) blks[blockIdx.x] = sm[1023];
}
__global__ void k_scan3b(const int* __restrict__ tmp, const int* __restrict__ blks,
                         const int* __restrict__ deg,
                         int* __restrict__ rowptr, int* __restrict__ cursor,
                         float* __restrict__ invdeg, int N) {
    __shared__ int bp;
    if (threadIdx.x == 0) {
        int s = 0;
        for (int b = 0; b < (int)blockIdx.x; b++) s += blks[b];
        bp = s;
    }
    __syncthreads();
    int i = blockIdx.x * 1024 + threadIdx.x;
    if (i < N) {
        int rp1 = tmp[i] + bp;
        rowptr[i + 1] = rp1;
        int d = deg[i];
        cursor[i] = rp1 - d;
        invdeg[i] = 1.0f / (float)max(d, 1);
    }
    if (i == 0) rowptr[0] = 0;
}
// 4 edges per thread, int4 loads
__global__ void k_fill4(const int* __restrict__ src, const int* __restrict__ dst,
                        int* __restrict__ cursor, int* __restrict__ srcs, int E) {
    int q = blockIdx.x * blockDim.x + threadIdx.x;
    int e = q * 4;
    if (e + 3 < E) {
        int4 d = *(const int4*)(dst + e);
        int4 s = *(const int4*)(src + e);
        int p0 = atomicAdd(&cursor[d.x], 1);
        int p1 = atomicAdd(&cursor[d.y], 1);
        int p2 = atomicAdd(&cursor[d.z], 1);
        int p3 = atomicAdd(&cursor[d.w], 1);
        srcs[p0] = s.x; srcs[p1] = s.y; srcs[p2] = s.z; srcs[p3] = s.w;
    } else {
        for (; e < E; e++) {
            int p = atomicAdd(&cursor[dst[e]], 1);
            srcs[p] = src[e];
        }
    }
}

// ---------------- weight split fp32 -> bf16 hi/lo ----------------
__global__ void k_wsplit(const float* __restrict__ proj_w, const float* __restrict__ lin_l_w,
                         const float* __restrict__ lin_r_w,
                         __nv_bfloat16* __restrict__ whi, __nv_bfloat16* __restrict__ wlo) {
    int i = blockIdx.x * blockDim.x + threadIdx.x;
    if (i >= 7 * 16384) return;
    int m = i >> 14, e = i & 16383;
    float v = (m == 0) ? proj_w[e] : (m <= 3 ? lin_l_w[(m - 1) * 16384 + e]
                                             : lin_r_w[(m - 4) * 16384 + e]);
    __nv_bfloat16 h = __float2bfloat16(v);
    whi[i] = h;
    wlo[i] = __float2bfloat16(v - __bfloat162float(h));
}

// ---------------- mean aggregation: warp per node, x4 unrolled (R12 proven) -------
__global__ void k_aggregate(const float* __restrict__ h, const int* __restrict__ rowptr,
                            const int* __restrict__ srcs, const float* __restrict__ invdeg,
                            __nv_bfloat16* __restrict__ ahi, __nv_bfloat16* __restrict__ alo,
                            int N) {
    int node = blockIdx.x * (blockDim.x >> 5) + (threadIdx.x >> 5);
    if (node >= N) return;
    int lane = threadIdx.x & 31;
    float ax = 0.f, ay = 0.f, az = 0.f, aw = 0.f;
    int e0 = rowptr[node], e1 = rowptr[node + 1];
    int e = e0;
    for (; e + 3 < e1; e += 4) {
        int s0 = __ldg(&srcs[e]);
        int s1 = __ldg(&srcs[e + 1]);
        int s2 = __ldg(&srcs[e + 2]);
        int s3 = __ldg(&srcs[e + 3]);
        float4 v0 = __ldg((const float4*)(h + (size_t)s0 * D + lane * 4));
        float4 v1 = __ldg((const float4*)(h + (size_t)s1 * D + lane * 4));
        float4 v2 = __ldg((const float4*)(h + (size_t)s2 * D + lane * 4));
        float4 v3 = __ldg((const float4*)(h + (size_t)s3 * D + lane * 4));
        ax += v0.x + v1.x + v2.x + v3.x;
        ay += v0.y + v1.y + v2.y + v3.y;
        az += v0.z + v1.z + v2.z + v3.z;
        aw += v0.w + v1.w + v2.w + v3.w;
    }
    for (; e < e1; e++) {
        int s = __ldg(&srcs[e]);
        float4 v = __ldg((const float4*)(h + (size_t)s * D + lane * 4));
        ax += v.x; ay += v.y; az += v.z; aw += v.w;
    }
    float id = invdeg[node];
    ax *= id; ay *= id; az *= id; aw *= id;
    size_t off = (size_t)node * D + lane * 4;
    *(uint2*)(ahi + off) = make_uint2(pack_hi2(ax, ay), pack_hi2(az, aw));
    *(uint2*)(alo + off) = make_uint2(pack_lo2(ax, ay), pack_lo2(az, aw));
}

// ---------------- mma.sync helpers ----------------
__device__ __forceinline__ void ldsm4(uint32_t* r, uint32_t saddr) {
    asm volatile("ldmatrix.sync.aligned.m8n8.x4.shared.b16 {%0,%1,%2,%3}, [%4];"
                 : "=r"(r[0]), "=r"(r[1]), "=r"(r[2]), "=r"(r[3]) : "r"(saddr));
}
__device__ __forceinline__ void mma_bf16(float* c, const uint32_t* a, uint32_t b0, uint32_t b1) {
    asm volatile(
        "mma.sync.aligned.m16n8k16.row.col.f32.bf16.bf16.f32 "
        "{%0,%1,%2,%3}, {%4,%5,%6,%7}, {%8,%9}, {%0,%1,%2,%3};"
        : "+f"(c[0]), "+f"(c[1]), "+f"(c[2]), "+f"(c[3])
        : "r"(a[0]), "r"(a[1]), "r"(a[2]), "r"(a[3]), "r"(b0), "r"(b1));
}

// =================== HMMA multi-GEMM + bias/relu/LN/resid (+head) ===================
// Block = 64x128 tile, 256 threads, warp grid 2(M)x4(N); warp tile 32x32. 2 CTAs/SM.
// Passes: 0 = A1(agg, pre-split) @ W1; 1 = A2f(h fp32, split in-kernel) @ W2;
//         2 (optional) = reuse A2 tile @ W3 -> acc2 (fused input-proj residual).
#define OFF_AHI 0
#define OFF_ALO (TILE_M * TSTR * 2)
#define OFF_BHI (2 * TILE_M * TSTR * 2)
#define OFF_BLO (OFF_BHI + 128 * TSTR * 2)
#define OFF_PAR (OFF_BLO + 128 * TSTR * 2)
#define SMEM_BYTES (OFF_PAR + 5 * 512)

__global__ void __launch_bounds__(THREADS, 2)
k_tcgemm(const __nv_bfloat16* __restrict__ A1hi, const __nv_bfloat16* __restrict__ A1lo,
         const float* __restrict__ A2f,
         const __nv_bfloat16* __restrict__ Whi1, const __nv_bfloat16* __restrict__ Wlo1,
         const __nv_bfloat16* __restrict__ Whi2, const __nv_bfloat16* __restrict__ Wlo2,
         const __nv_bfloat16* __restrict__ Whi3, const __nv_bfloat16* __restrict__ Wlo3,
         const float* __restrict__ bias, const float* __restrict__ pb,
         const float* __restrict__ lng, const float* __restrict__ lnb,
         const float* __restrict__ resid,
         float* __restrict__ outp,
         const float* __restrict__ hw, const float* __restrict__ hb,
         const float* __restrict__ rer, const float* __restrict__ alpha,
         float* __restrict__ score, int M) {
    extern __shared__ __align__(16) char sg[];
    uint32_t sb = (uint32_t)__cvta_generic_to_shared(sg);

    int tid  = threadIdx.x;
    int lane = tid & 31;
    int wid  = tid >> 5;
    int wm   = wid >> 2;          // m offset wm*32
    int wn   = wid & 3;           // n offset wn*32
    int row0 = blockIdx.x * TILE_M;

    float* bias_s = (float*)(sg + OFF_PAR);
    float* lng_s  = (float*)(sg + OFF_PAR + 512);
    float* lnb_s  = (float*)(sg + OFF_PAR + 1024);
    float* hw_s   = (float*)(sg + OFF_PAR + 1536);
    float* pb_s   = (float*)(sg + OFF_PAR + 2048);
    float* Sg     = (float*)sg;                 // acc staging 64x132 fp32
    float* Sg2    = (float*)sg + 64 * 132;      // acc2 staging (proj residual)

    if (tid < 128) {
        bias_s[tid] = bias ? bias[tid] : 0.f;
        lng_s[tid]  = lng ? lng[tid] : 1.f;
        lnb_s[tid]  = lnb ? lnb[tid] : 0.f;
        hw_s[tid]   = hw  ? hw[tid]  : 0.f;
        pb_s[tid]   = pb  ? pb[tid]  : 0.f;
    }

    float acc[2][4][4], acc2[2][4][4];
#pragma unroll
    for (int mt = 0; mt < 2; mt++)
#pragma unroll
        for (int nt = 0; nt < 4; nt++)
#pragma unroll
            for (int c = 0; c < 4; c++) { acc[mt][nt][c] = 0.f; acc2[mt][nt][c] = 0.f; }

    int frow = lane & 15;
    int fcol = (lane >> 4) * 8;
    uint32_t aoff = (uint32_t)(((wm * 32 + frow) * TSTR + fcol) * 2);
    uint32_t boff = (uint32_t)(((wn * 32 + frow) * TSTR + fcol) * 2);

    auto mma_phase = [&](float (*ac)[4][4]) {
#pragma unroll
        for (int ks = 0; ks < 8; ks++) {
            uint32_t kb = (uint32_t)(ks * 32);
            uint32_t ah[2][4], al[2][4], bh[2][4], bl[2][4];
#pragma unroll
            for (int mt = 0; mt < 2; mt++) {
                ldsm4(ah[mt], sb + OFF_AHI + aoff + mt * 16 * TSTR * 2 + kb);
                ldsm4(al[mt], sb + OFF_ALO + aoff + mt * 16 * TSTR * 2 + kb);
            }
#pragma unroll
            for (int p = 0; p < 2; p++) {
                ldsm4(bh[p], sb + OFF_BHI + boff + p * 16 * TSTR * 2 + kb);
                ldsm4(bl[p], sb + OFF_BLO + boff + p * 16 * TSTR * 2 + kb);
            }
#pragma unroll
            for (int mt = 0; mt < 2; mt++) {
#pragma unroll
                for (int nt = 0; nt < 4; nt++) {
                    int p = nt >> 1, q = nt & 1;
                    mma_bf16(ac[mt][nt], ah[mt], bh[p][q], bh[p][q + 2]);  // hi*hi
                    mma_bf16(ac[mt][nt], ah[mt], bl[p][q], bl[p][q + 2]);  // hi*lo
                    mma_bf16(ac[mt][nt], al[mt], bh[p][q], bh[p][q + 2]);  // lo*hi
                }
            }
        }
    };

    int npass = (Whi3 != nullptr) ? 3 : 2;
    const __nv_bfloat16* Whis[3] = {Whi1, Whi2, Whi3};
    const __nv_bfloat16* Wlos[3] = {Wlo1, Wlo2, Wlo3};

    for (int pass = 0; pass < npass; pass++) {
        const __nv_bfloat16* Whi = Whis[pass];
        const __nv_bfloat16* Wlo = Wlos[pass];

        // W tiles via cp.async: 128 rows x 16 chunks of 16B
#pragma unroll
        for (int it = 0; it < 8; it++) {
            int u = tid + it * 256;
            int n = u >> 4, c16 = u & 15;
            uint32_t doff = (uint32_t)(n * TSTR * 2 + c16 * 16);
            const size_t gs = (size_t)n * 128 + c16 * 8;
            asm volatile("cp.async.ca.shared.global [%0], [%1], 16;"
                         :: "r"(sb + OFF_BHI + doff), "l"(Whi + gs));
            asm volatile("cp.async.ca.shared.global [%0], [%1], 16;"
                         :: "r"(sb + OFF_BLO + doff), "l"(Wlo + gs));
        }

        if (pass == 0) {
            // pre-split A1 (agg): cp.async, 64 rows x 16 chunks
#pragma unroll
            for (int it = 0; it < 4; it++) {
                int u = tid + it * 256;
                int r = u >> 4, c16 = u & 15;
                uint32_t doff = (uint32_t)(r * TSTR * 2 + c16 * 16);
                const size_t gs = (size_t)(row0 + r) * D + c16 * 8;
                asm volatile("cp.async.ca.shared.global [%0], [%1], 16;"
                             :: "r"(sb + OFF_AHI + doff), "l"(A1hi + gs));
                asm volatile("cp.async.ca.shared.global [%0], [%1], 16;"
                             :: "r"(sb + OFF_ALO + doff), "l"(A1lo + gs));
            }
            asm volatile("cp.async.commit_group;");
        } else if (pass == 1) {
            asm volatile("cp.async.commit_group;");
            // fp32 A2 -> split in-kernel
#pragma unroll
            for (int it = 0; it < 8; it++) {
                int idx = tid + it * 256;
                int r = idx >> 5, k4 = (idx & 31);
                float4 v = make_float4(0.f, 0.f, 0.f, 0.f);
                int grow = row0 + r;
                if (grow < M) v = *(const float4*)(A2f + (size_t)grow * D + k4 * 4);
                int doff = r * TSTR * 2 + k4 * 8;
                *(uint2*)(sg + OFF_AHI + doff) = make_uint2(pack_hi2(v.x, v.y), pack_hi2(v.z, v.w));
                *(uint2*)(sg + OFF_ALO + doff) = make_uint2(pack_lo2(v.x, v.y), pack_lo2(v.z, v.w));
            }
        } else {
            asm volatile("cp.async.commit_group;");
            // pass 2: reuse A tile from pass 1
        }

        asm volatile("cp.async.wait_group 0;");
        __syncthreads();

        if (pass == 2) mma_phase(acc2);
        else           mma_phase(acc);
        __syncthreads();
    }

    // ---- stage accumulators to SMEM ----
#pragma unroll
    for (int mt = 0; mt < 2; mt++) {
#pragma unroll
        for (int nt = 0; nt < 4; nt++) {
            int m = wm * 32 + mt * 16 + (lane >> 2);
            int n = wn * 32 + nt * 8 + (lane & 3) * 2;
            *(float2*)&Sg[m * 132 + n]       = make_float2(acc[mt][nt][0], acc[mt][nt][1]);
            *(float2*)&Sg[(m + 8) * 132 + n] = make_float2(acc[mt][nt][2], acc[mt][nt][3]);
            if (npass == 3) {
                *(float2*)&Sg2[m * 132 + n]       = make_float2(acc2[mt][nt][0], acc2[mt][nt][1]);
                *(float2*)&Sg2[(m + 8) * 132 + n] = make_float2(acc2[mt][nt][2], acc2[mt][nt][3]);
            }
        }
    }
    __syncthreads();

    // ---- per-row epilogue; warp owns 8 rows, lane owns cols lane*4..+3 ----
    int cb = lane * 4;
#pragma unroll
    for (int rr = 0; rr < 8; rr++) {
        int row_l = wid * 8 + rr;
        int grow = row0 + row_l;
        if (grow >= M) break;
        float v[4];
#pragma unroll
        for (int cc = 0; cc < 4; cc++)
            v[cc] = Sg[row_l * 132 + cb + cc] + bias_s[cb + cc];
        // relu + LN
#pragma unroll
        for (int cc = 0; cc < 4; cc++) v[cc] = fmaxf(v[cc], 0.f);
        float s = v[0] + v[1] + v[2] + v[3];
#pragma unroll
        for (int o = 16; o > 0; o >>= 1) s += __shfl_xor_sync(0xffffffffu, s, o);
        float mu = s * (1.f / 128.f);
        float d0 = v[0] - mu, d1 = v[1] - mu, d2 = v[2] - mu, d3 = v[3] - mu;
        float q = d0 * d0 + d1 * d1 + d2 * d2 + d3 * d3;
#pragma unroll
        for (int o = 16; o > 0; o >>= 1) q += __shfl_xor_sync(0xffffffffu, q, o);
        float rs = rsqrtf(q * (1.f / 128.f) + EPSL);
        v[0] = d0 * rs * lng_s[cb]     + lnb_s[cb];
        v[1] = d1 * rs * lng_s[cb + 1] + lnb_s[cb + 1];
        v[2] = d2 * rs * lng_s[cb + 2] + lnb_s[cb + 2];
        v[3] = d3 * rs * lng_s[cb + 3] + lnb_s[cb + 3];
        if (npass == 3) {
            // fused input-proj residual: acc2 + proj_b
#pragma unroll
            for (int cc = 0; cc < 4; cc++)
                v[cc] += Sg2[row_l * 132 + cb + cc] + pb_s[cb + cc];
        } else {
            float4 rz = *(const float4*)(resid + (size_t)grow * D + cb);
            v[0] += rz.x; v[1] += rz.y; v[2] += rz.z; v[3] += rz.w;
        }
        if (score) {
            float sd = v[0] * hw_s[cb] + v[1] * hw_s[cb + 1]
                     + v[2] * hw_s[cb + 2] + v[3] * hw_s[cb + 3];
#pragma unroll
            for (int o = 16; o > 0; o >>= 1) sd += __shfl_xor_sync(0xffffffffu, sd, o);
            if (lane == 0) {
                float gnn = sd + hb[0];
                float a = 1.f / (1.f + expf(-alpha[0]));
                score[grow] = a * rer[grow] + (1.f - a) * gnn;
            }
        } else {
            *(float4*)(outp + (size_t)grow * D + cb) = make_float4(v[0], v[1], v[2], v[3]);
        }
    }
}

// ---------------- launch ----------------
extern "C" void kernel_launch(void* const* d_in, const int* in_sizes, int n_in,
                              void* d_out, int out_size) {
    const float* x       = (const float*)d_in[0];
    const int*   ei      = (const int*)  d_in[1];
    const float* rer     = (const float*)d_in[2];
    const float* proj_w  = (const float*)d_in[3];
    const float* proj_b  = (const float*)d_in[4];
    const float* lin_l_w = (const float*)d_in[5];
    const float* lin_l_b = (const float*)d_in[6];
    const float* lin_r_w = (const float*)d_in[7];
    const float* ln_g    = (const float*)d_in[8];
    const float* ln_b    = (const float*)d_in[9];
    const float* head_w  = (const float*)d_in[10];
    const float* head_b  = (const float*)d_in[11];
    const float* alpha   = (const float*)d_in[12];

    int N = in_sizes[0] / D;
    int E = in_sizes[1] / 2;
    const int* src = ei;
    const int* dst = ei + E;
    float* out = (float*)d_out;

    float *h0, *h1, *invdeg;
    int *deg, *rowptr, *cursor, *stmp, *blks, *srcs;
    __nv_bfloat16 *whi, *wlo, *ahi, *alo;
    cudaGetSymbolAddress((void**)&h0,     g_h0);
    cudaGetSymbolAddress((void**)&h1,     g_h1);
    cudaGetSymbolAddress((void**)&invdeg, g_invdeg);
    cudaGetSymbolAddress((void**)&deg,    g_deg);
    cudaGetSymbolAddress((void**)&rowptr, g_rowptr);
    cudaGetSymbolAddress((void**)&cursor, g_cursor);
    cudaGetSymbolAddress((void**)&stmp,   g_scantmp);
    cudaGetSymbolAddress((void**)&blks,   g_blksums);
    cudaGetSymbolAddress((void**)&srcs,   g_srcsorted);
    cudaGetSymbolAddress((void**)&whi,    g_whi);
    cudaGetSymbolAddress((void**)&wlo,    g_wlo);
    cudaGetSymbolAddress((void**)&ahi,    g_agghi);
    cudaGetSymbolAddress((void**)&alo,    g_agglo);

    // lazy one-time stream/event creation (no device memory allocation)
    static cudaStream_t s2 = nullptr;
    static cudaEvent_t evFork = nullptr, evJoin = nullptr;
    if (s2 == nullptr) {
        cudaStreamCreateWithFlags(&s2, cudaStreamNonBlocking);
        cudaEventCreateWithFlags(&evFork, cudaEventDisableTiming);
        cudaEventCreateWithFlags(&evJoin, cudaEventDisableTiming);
    }

    int nb = (N + 1023) / 1024;
    cudaFuncSetAttribute(k_tcgemm, cudaFuncAttributeMaxDynamicSharedMemorySize, SMEM_BYTES);
    int blocks = (N + TILE_M - 1) / TILE_M;
    int warp_blocks = (N + 7) / 8;
    int equads = (E + 3) / 4;
    const size_t WM = 128 * 128;

    // ---- fork: branch B (s2) = wsplit; branch A (default) = CSR ----
    cudaEventRecord(evFork, 0);
    cudaStreamWaitEvent(s2, evFork, 0);

    k_wsplit<<<(7 * 16384 + 255) / 256, 256, 0, s2>>>(proj_w, lin_l_w, lin_r_w, whi, wlo);

    k_zero  <<<(N + 255) / 256, 256>>>(deg, rowptr, N);
    k_count4<<<(equads + 255) / 256, 256>>>(dst, deg, E);
    k_scan1 <<<nb, 1024>>>(deg, stmp, blks, N);
    k_scan3b<<<nb, 1024>>>(stmp, blks, deg, rowptr, cursor, invdeg, N);
    k_fill4 <<<(equads + 255) / 256, 256>>>(src, dst, cursor, srcs, E);

    cudaEventRecord(evJoin, s2);
    cudaStreamWaitEvent(0, evJoin, 0);

    // ---- layers; layer 0 fuses the input-proj residual as a 3rd MMA pass ----
    const float* h_cur = x;
    float* bufs[2] = {h0, h1};
    for (int i = 0; i < 3; i++) {
        bool last = (i == 2);
        k_aggregate<<<warp_blocks, 256>>>(h_cur, rowptr, srcs, invdeg, ahi, alo, N);
        k_tcgemm<<<blocks, THREADS, SMEM_BYTES>>>(
            ahi, alo, h_cur,
            whi + (1 + i) * WM, wlo + (1 + i) * WM,
            whi + (4 + i) * WM, wlo + (4 + i) * WM,
            (i == 0) ? whi : nullptr,          // W3 = proj (layer 0 only)
            (i == 0) ? wlo : nullptr,
            lin_l_b + (size_t)i * D,
            (i == 0) ? proj_b : nullptr,
            ln_g + (size_t)i * D, ln_b + (size_t)i * D,
            (i == 0) ? nullptr : h_cur,        // resid: global h for layers 1,2
            last ? nullptr : bufs[i & 1],
            last ? head_w : nullptr,
            last ? head_b : nullptr,
            last ? rer    : nullptr,
            last ? alpha  : nullptr,
            last ? out    : nullptr, N);
        h_cur = bufs[i & 1];
    }
}